// round 5
// baseline (speedup 1.0000x reference)
#include <cuda_runtime.h>
#include <math.h>

#define BB   32
#define HH   128
#define WWD  128
#define CC   80
#define DHH  10
#define NHH  8
#define NTOK (BB*HH*WWD)      // 524288
#define NWIN 8192

// ---- scratch (allocation-free: device globals) ----
__device__ float g_t1[(size_t)NTOK * CC];
__device__ float g_t2[(size_t)NTOK * CC];

__device__ __forceinline__ float warp_sum(float v) {
    v += __shfl_xor_sync(0xffffffffu, v, 16);
    v += __shfl_xor_sync(0xffffffffu, v, 8);
    v += __shfl_xor_sync(0xffffffffu, v, 4);
    v += __shfl_xor_sync(0xffffffffu, v, 2);
    v += __shfl_xor_sync(0xffffffffu, v, 1);
    return v;
}

template<bool GRIDMODE>
__device__ __forceinline__ size_t tok_base(int b, int r0, int c0, int t) {
    int i = t >> 3, j = t & 7;
    int hh, ww;
    if (!GRIDMODE) { hh = r0 * 8 + i;  ww = c0 * 8 + j;  }
    else           { hh = i * 16 + r0; ww = j * 16 + c0; }
    return ((size_t)((b * HH + hh) * WWD + ww)) * CC;
}

// ============================================================================
// Attention kernel: one CTA per 64-token window. smem ~70KB -> 3 CTAs/SM.
// q/k/v resident; normalized x streamed through a 32-token half buffer;
// residual recomputed from global x using stored 1/||x||.
// ============================================================================
template<bool GRIDMODE>
__global__ __launch_bounds__(256, 3)
void attn_kernel(const float* __restrict__ xin,
                 const float* __restrict__ wqkv, const float* __restrict__ bqkv,
                 const float* __restrict__ wproj, const float* __restrict__ bproj,
                 float* __restrict__ yout)
{
    extern __shared__ float sm[];
    float* sq   = sm;             // 64x80
    float* sk   = sm + 5120;      // 64x80
    float* sv   = sm + 10240;     // 64x80
    float* xh   = sm + 15360;     // 32x80 (half buffer of normalized x)
    float* sinv = sm + 17920;     // 64 inv-norms

    const int tid  = threadIdx.x;
    const int lane = tid & 31;
    const int wid  = tid >> 5;

    const int wblk = blockIdx.x;
    const int b    = wblk >> 8;
    const int rem  = wblk & 255;
    const int r0   = rem >> 4;
    const int c0   = rem & 15;

    // ---- phase 1: two halves of 32 tokens: load+norm -> qkv ----
    #pragma unroll 1
    for (int half = 0; half < 2; ++half) {
        // each warp: its own 4 tokens (no cross-warp deps in this phase)
        #pragma unroll
        for (int r = 0; r < 4; ++r) {
            const int tl = wid * 4 + r;             // 0..31
            const int t  = half * 32 + tl;
            const float* p = xin + tok_base<GRIDMODE>(b, r0, c0, t);
            float v0 = p[lane];
            float v1 = p[lane + 32];
            float v2 = (lane < 16) ? p[lane + 64] : 0.f;
            float s  = warp_sum(v0*v0 + v1*v1 + v2*v2);
            float inv = 1.f / fmaxf(sqrtf(s), 1e-12f);
            float* xr = xh + tl * CC;
            xr[lane]      = v0 * inv;
            xr[lane + 32] = v1 * inv;
            if (lane < 16) xr[lane + 64] = v2 * inv;
            if (lane == 0) sinv[t] = inv;
        }
        __syncwarp();

        // qkv: warp -> its 4 tokens, thread -> 8 columns
        {
            const float* xr = xh + wid * 4 * CC;
            int cs[8];
            float acc[4][8];
            #pragma unroll
            for (int g = 0; g < 8; ++g) {
                int c = lane + 32 * g;
                cs[g] = (c < 240) ? c : 239;
                float bias = bqkv[cs[g]];
                #pragma unroll
                for (int r = 0; r < 4; ++r) acc[r][g] = bias;
            }
            #pragma unroll 1
            for (int j4 = 0; j4 < 20; ++j4) {
                float4 xv[4];
                #pragma unroll
                for (int r = 0; r < 4; ++r)
                    xv[r] = *reinterpret_cast<const float4*>(xr + r * CC + j4 * 4);
                const float* xf = reinterpret_cast<const float*>(xv);
                #pragma unroll
                for (int jj = 0; jj < 4; ++jj) {
                    const float* wrow = wqkv + (j4 * 4 + jj) * 240;
                    float wv[8];
                    #pragma unroll
                    for (int g = 0; g < 8; ++g) wv[g] = __ldg(wrow + cs[g]);
                    #pragma unroll
                    for (int g = 0; g < 8; ++g)
                        #pragma unroll
                        for (int r = 0; r < 4; ++r)
                            acc[r][g] = fmaf(xf[r * 4 + jj], wv[g], acc[r][g]);
                }
            }
            #pragma unroll
            for (int g = 0; g < 8; ++g) {
                int c = lane + 32 * g;
                if (c < 240) {
                    int hd = c / 30, rm = c % 30, s3 = rm / 10, d = rm % 10;
                    float* dst = ((s3 == 0) ? sq : (s3 == 1) ? sk : sv) + hd * DHH + d;
                    const int trow = half * 32 + wid * 4;
                    #pragma unroll
                    for (int r = 0; r < 4; ++r)
                        dst[(trow + r) * CC] = acc[r][g];
                }
            }
        }
        __syncwarp();   // xh reused next half by same warp only
    }
    __syncthreads();    // all q/k/v and sinv visible CTA-wide

    // ---- phase 2: attention, one head per warp, exp2-domain softmax ----
    {
        const int hd = wid;
        const float* qb = sq + hd * DHH;
        const float* kb = sk + hd * DHH;
        const float* vb = sv + hd * DHH;
        const float qscale = 0.31622776601683794f * 1.4426950408889634f; // d^-.5 * log2e
        float q0[10], q1[10], o0[10], o1[10];
        #pragma unroll
        for (int d = 0; d < 10; ++d) {
            q0[d] = qb[lane * CC + d] * qscale;
            q1[d] = qb[(lane + 32) * CC + d] * qscale;
            o0[d] = 0.f; o1[d] = 0.f;
        }
        float m0 = -1e30f, m1 = -1e30f, l0 = 0.f, l1 = 0.f;
        #pragma unroll 1
        for (int kk = 0; kk < 64; ++kk) {
            float kv[10], vv[10];
            #pragma unroll
            for (int d2 = 0; d2 < 5; ++d2) {
                float2 kt = *reinterpret_cast<const float2*>(kb + kk * CC + d2 * 2);
                float2 vt = *reinterpret_cast<const float2*>(vb + kk * CC + d2 * 2);
                kv[d2*2] = kt.x; kv[d2*2+1] = kt.y;
                vv[d2*2] = vt.x; vv[d2*2+1] = vt.y;
            }
            float s0 = 0.f, s1 = 0.f;
            #pragma unroll
            for (int d = 0; d < 10; ++d) { s0 = fmaf(q0[d], kv[d], s0); s1 = fmaf(q1[d], kv[d], s1); }

            float nm0 = fmaxf(m0, s0);
            float cf0 = exp2f(m0 - nm0);
            float p0  = exp2f(s0 - nm0);
            l0 = l0 * cf0 + p0;
            #pragma unroll
            for (int d = 0; d < 10; ++d) o0[d] = fmaf(o0[d], cf0, p0 * vv[d]);
            m0 = nm0;

            float nm1 = fmaxf(m1, s1);
            float cf1 = exp2f(m1 - nm1);
            float p1  = exp2f(s1 - nm1);
            l1 = l1 * cf1 + p1;
            #pragma unroll
            for (int d = 0; d < 10; ++d) o1[d] = fmaf(o1[d], cf1, p1 * vv[d]);
            m1 = nm1;
        }
        const float il0 = 1.f / l0, il1 = 1.f / l1;
        float* ob = sq + hd * DHH;       // overwrite q columns for this head
        #pragma unroll
        for (int d = 0; d < 10; ++d) {
            ob[lane * CC + d]        = o0[d] * il0;
            ob[(lane + 32) * CC + d] = o1[d] * il1;
        }
    }
    __syncthreads();

    // ---- phase 3: proj + residual(recomputed) + scatter: warp -> 8 tokens ----
    {
        const float* ob = sq + wid * 8 * CC;
        int cs[3];
        cs[0] = lane; cs[1] = lane + 32; cs[2] = (lane < 16) ? (lane + 64) : 79;
        float acc[8][3];
        #pragma unroll
        for (int g = 0; g < 3; ++g) {
            float bias = bproj[cs[g]];
            #pragma unroll
            for (int r = 0; r < 8; ++r) acc[r][g] = bias;
        }
        #pragma unroll 1
        for (int j4 = 0; j4 < 20; ++j4) {
            #pragma unroll
            for (int rb = 0; rb < 2; ++rb) {        // 4 tokens at a time (reg pressure)
                float4 ov[4];
                #pragma unroll
                for (int r = 0; r < 4; ++r)
                    ov[r] = *reinterpret_cast<const float4*>(ob + (rb*4 + r) * CC + j4 * 4);
                const float* of = reinterpret_cast<const float*>(ov);
                #pragma unroll
                for (int jj = 0; jj < 4; ++jj) {
                    const float* wrow = wproj + (j4 * 4 + jj) * CC;
                    float wv[3];
                    #pragma unroll
                    for (int g = 0; g < 3; ++g) wv[g] = __ldg(wrow + cs[g]);
                    #pragma unroll
                    for (int g = 0; g < 3; ++g)
                        #pragma unroll
                        for (int r = 0; r < 4; ++r)
                            acc[rb*4 + r][g] = fmaf(of[r * 4 + jj], wv[g], acc[rb*4 + r][g]);
                }
            }
        }
        #pragma unroll
        for (int r = 0; r < 8; ++r) {
            const int t = wid * 8 + r;
            const size_t base = tok_base<GRIDMODE>(b, r0, c0, t);
            const float inv = sinv[t];
            yout[base + cs[0]] = __ldg(xin + base + cs[0]) * inv + acc[r][0];
            yout[base + cs[1]] = __ldg(xin + base + cs[1]) * inv + acc[r][1];
            if (lane < 16)
                yout[base + cs[2]] = __ldg(xin + base + cs[2]) * inv + acc[r][2];
        }
    }
}

// ============================================================================
// MLP kernel: one CTA per 32 contiguous tokens. smem 50KB -> 4 CTAs/SM.
// Warps fully independent (4 tokens each) -> no CTA-wide syncs.
// ============================================================================
template<bool RELU2>
__global__ __launch_bounds__(256, 4)
void mlp_kernel(const float* __restrict__ xin,
                const float* __restrict__ w1,
                const float* __restrict__ w2,
                const float* __restrict__ b2,
                const float* __restrict__ gamma,
                float* __restrict__ yout)
{
    extern __shared__ float sm[];
    float* xn = sm;            // 32x80
    float* hb = sm + 2560;     // 32x320

    const int tid  = threadIdx.x;
    const int lane = tid & 31;
    const int wid  = tid >> 5;
    const size_t base = (size_t)blockIdx.x * 32 * CC;

    // ---- load + l2norm: warp -> its 4 tokens ----
    #pragma unroll
    for (int r = 0; r < 4; ++r) {
        const int t = wid * 4 + r;
        const float* p = xin + base + (size_t)t * CC;
        float v0 = p[lane];
        float v1 = p[lane + 32];
        float v2 = (lane < 16) ? p[lane + 64] : 0.f;
        float s  = warp_sum(v0*v0 + v1*v1 + v2*v2);
        float inv = 1.f / fmaxf(sqrtf(s), 1e-12f);
        float* xr = xn + t * CC;
        xr[lane]      = v0 * inv;
        xr[lane + 32] = v1 * inv;
        if (lane < 16) xr[lane + 64] = v2 * inv;
    }
    __syncwarp();

    // ---- h = relu(xn @ W1): warp -> 4 tokens, thread -> 10 cols (2 halves) ----
    {
        const float* xr = xn + wid * 4 * CC;
        float* hr = hb + wid * 4 * 320;
        #pragma unroll 1
        for (int half = 0; half < 2; ++half) {
            const int cbase = half * 160 + lane;
            float acc[4][5];
            #pragma unroll
            for (int g = 0; g < 5; ++g)
                #pragma unroll
                for (int r = 0; r < 4; ++r) acc[r][g] = 0.f;
            #pragma unroll 1
            for (int j4 = 0; j4 < 20; ++j4) {
                float4 xv[4];
                #pragma unroll
                for (int r = 0; r < 4; ++r)
                    xv[r] = *reinterpret_cast<const float4*>(xr + r * CC + j4 * 4);
                const float* xf = reinterpret_cast<const float*>(xv);
                #pragma unroll
                for (int jj = 0; jj < 4; ++jj) {
                    const float* wrow = w1 + (j4 * 4 + jj) * 320 + cbase;
                    float wv[5];
                    #pragma unroll
                    for (int g = 0; g < 5; ++g) wv[g] = __ldg(wrow + 32 * g);
                    #pragma unroll
                    for (int g = 0; g < 5; ++g)
                        #pragma unroll
                        for (int r = 0; r < 4; ++r)
                            acc[r][g] = fmaf(xf[r * 4 + jj], wv[g], acc[r][g]);
                }
            }
            #pragma unroll
            for (int g = 0; g < 5; ++g)
                #pragma unroll
                for (int r = 0; r < 4; ++r)
                    hr[r * 320 + cbase + 32 * g] = fmaxf(acc[r][g], 0.f);
        }
    }
    __syncwarp();

    // ---- out = xn + act(h @ W2 + b2) * gamma : warp -> 4 tokens, 3 cols ----
    {
        const float* hr = hb + wid * 4 * 320;
        int cs[3];
        cs[0] = lane; cs[1] = lane + 32; cs[2] = (lane < 16) ? (lane + 64) : 79;
        float acc[4][3];
        #pragma unroll
        for (int g = 0; g < 3; ++g) {
            float bias = b2[cs[g]];
            #pragma unroll
            for (int r = 0; r < 4; ++r) acc[r][g] = bias;
        }
        #pragma unroll 1
        for (int j4 = 0; j4 < 80; ++j4) {
            float4 hv[4];
            #pragma unroll
            for (int r = 0; r < 4; ++r)
                hv[r] = *reinterpret_cast<const float4*>(hr + r * 320 + j4 * 4);
            const float* hf = reinterpret_cast<const float*>(hv);
            #pragma unroll
            for (int jj = 0; jj < 4; ++jj) {
                const float* wrow = w2 + (j4 * 4 + jj) * CC;
                float wv[3];
                #pragma unroll
                for (int g = 0; g < 3; ++g) wv[g] = __ldg(wrow + cs[g]);
                #pragma unroll
                for (int g = 0; g < 3; ++g)
                    #pragma unroll
                    for (int r = 0; r < 4; ++r)
                        acc[r][g] = fmaf(hf[r * 4 + jj], wv[g], acc[r][g]);
            }
        }
        #pragma unroll
        for (int g = 0; g < 3; ++g) {
            const float gm = gamma[cs[g]];
            #pragma unroll
            for (int r = 0; r < 4; ++r) {
                float v = acc[r][g];
                if (RELU2) v = fmaxf(v, 0.f);
                const int t = wid * 4 + r;
                if (g < 2 || lane < 16)
                    yout[base + (size_t)t * CC + cs[g]] = xn[t * CC + cs[g]] + v * gm;
            }
        }
    }
}

// ============================================================================
extern "C" void kernel_launch(void* const* d_in, const int* in_sizes, int n_in,
                              void* d_out, int out_size)
{
    const float* x       = (const float*)d_in[0];
    const float* bw_qkv  = (const float*)d_in[1];
    const float* bb_qkv  = (const float*)d_in[2];
    const float* bw_proj = (const float*)d_in[3];
    const float* bb_proj = (const float*)d_in[4];
    const float* b_gamma = (const float*)d_in[5];
    const float* bw_mlp1 = (const float*)d_in[6];
    const float* bw_mlp2 = (const float*)d_in[7];
    const float* bb_mlp2 = (const float*)d_in[8];
    const float* gw_qkv  = (const float*)d_in[9];
    const float* gb_qkv  = (const float*)d_in[10];
    const float* gw_proj = (const float*)d_in[11];
    const float* gb_proj = (const float*)d_in[12];
    const float* g_gamma = (const float*)d_in[13];
    const float* gw_mlp1 = (const float*)d_in[14];
    const float* gw_mlp2 = (const float*)d_in[15];
    const float* gb_mlp2 = (const float*)d_in[16];
    float* out = (float*)d_out;

    float *t1 = nullptr, *t2 = nullptr;
    cudaGetSymbolAddress((void**)&t1, g_t1);
    cudaGetSymbolAddress((void**)&t2, g_t2);

    const int ATTN_SMEM = (3 * 5120 + 2560 + 64) * (int)sizeof(float);  // 71936
    const int MLP_SMEM  = (2560 + 10240) * (int)sizeof(float);          // 51200

    static bool attrs_set = false;
    if (!attrs_set) {
        cudaFuncSetAttribute(attn_kernel<false>, cudaFuncAttributeMaxDynamicSharedMemorySize, ATTN_SMEM);
        cudaFuncSetAttribute(attn_kernel<true>,  cudaFuncAttributeMaxDynamicSharedMemorySize, ATTN_SMEM);
        cudaFuncSetAttribute(mlp_kernel<true>,   cudaFuncAttributeMaxDynamicSharedMemorySize, MLP_SMEM);
        cudaFuncSetAttribute(mlp_kernel<false>,  cudaFuncAttributeMaxDynamicSharedMemorySize, MLP_SMEM);
        attrs_set = true;
    }

    const int NB_MLP = NTOK / 32;   // 16384

    attn_kernel<false><<<NWIN, 256, ATTN_SMEM>>>(x,  bw_qkv, bb_qkv, bw_proj, bb_proj, t1);
    mlp_kernel<true><<<NB_MLP, 256, MLP_SMEM>>>(t1, bw_mlp1, bw_mlp2, bb_mlp2, b_gamma, t2);
    attn_kernel<true><<<NWIN, 256, ATTN_SMEM>>>(t2, gw_qkv, gb_qkv, gw_proj, gb_proj, t1);
    mlp_kernel<false><<<NB_MLP, 256, MLP_SMEM>>>(t1, gw_mlp1, gw_mlp2, gb_mlp2, g_gamma, out);
}

// round 6
// speedup vs baseline: 1.0111x; 1.0111x over previous
#include <cuda_runtime.h>
#include <math.h>

#define BB   32
#define HH   128
#define WWD  128
#define CC   80
#define DHH  10
#define NHH  8
#define NTOK (BB*HH*WWD)      // 524288
#define NWIN 8192
#define TSTR 66               // transposed-row stride (floats): even, +2 bank skew

typedef unsigned long long u64;

// ---- scratch (allocation-free: device globals) ----
__device__ float g_t1[(size_t)NTOK * CC];
__device__ float g_t2[(size_t)NTOK * CC];

// ---- packed fp32x2 helpers ----
__device__ __forceinline__ u64 pack2(float lo, float hi) {
    u64 r; asm("mov.b64 %0, {%1, %2};" : "=l"(r) : "f"(lo), "f"(hi)); return r;
}
__device__ __forceinline__ u64 dup2(float v) { return pack2(v, v); }
__device__ __forceinline__ void unpack2(u64 p, float& lo, float& hi) {
    asm("mov.b64 {%0, %1}, %2;" : "=f"(lo), "=f"(hi) : "l"(p));
}
__device__ __forceinline__ u64 fma2(u64 a, u64 b, u64 c) {
    u64 d; asm("fma.rn.f32x2 %0, %1, %2, %3;" : "=l"(d) : "l"(a), "l"(b), "l"(c)); return d;
}
__device__ __forceinline__ u64 mul2(u64 a, u64 b) {
    u64 d; asm("mul.rn.f32x2 %0, %1, %2;" : "=l"(d) : "l"(a), "l"(b)); return d;
}

__device__ __forceinline__ float warp_sum(float v) {
    v += __shfl_xor_sync(0xffffffffu, v, 16);
    v += __shfl_xor_sync(0xffffffffu, v, 8);
    v += __shfl_xor_sync(0xffffffffu, v, 4);
    v += __shfl_xor_sync(0xffffffffu, v, 2);
    v += __shfl_xor_sync(0xffffffffu, v, 1);
    return v;
}

template<bool GRIDMODE>
__device__ __forceinline__ size_t tok_base(int b, int r0, int c0, int t) {
    int i = t >> 3, j = t & 7;
    int hh, ww;
    if (!GRIDMODE) { hh = r0 * 8 + i;  ww = c0 * 8 + j;  }
    else           { hh = i * 16 + r0; ww = j * 16 + c0; }
    return ((size_t)((b * HH + hh) * WWD + ww)) * CC;
}

// ============================================================================
// Attention kernel: one CTA per 64-token window. smem ~101KB -> 2 CTAs/SM.
// xT (normalized x, transposed) + q/k/v (row-major) + oT (transposed attn out)
// ============================================================================
template<bool GRIDMODE>
__global__ __launch_bounds__(256, 2)
void attn_kernel(const float* __restrict__ xin,
                 const float* __restrict__ wqkv, const float* __restrict__ bqkv,
                 const float* __restrict__ wproj, const float* __restrict__ bproj,
                 float* __restrict__ yout)
{
    extern __shared__ float sm[];
    float* xT = sm;                    // 80 x 66   = 5280
    float* sq = sm + 5280;             // 64 x 80   = 5120
    float* sk = sm + 10400;            // 5120
    float* sv = sm + 15520;            // 5120
    float* oT = sm + 20640;            // 80 x 66   = 5280   (total 25920 fl)

    const int tid  = threadIdx.x;
    const int lane = tid & 31;
    const int wid  = tid >> 5;
    const int t0   = wid * 8;

    const int wblk = blockIdx.x;
    const int b    = wblk >> 8;
    const int rem  = wblk & 255;
    const int r0   = rem >> 4;
    const int c0   = rem & 15;

    // ---- phase 1: load + l2norm -> xT (warp owns its 8 tokens) ----
    #pragma unroll
    for (int r = 0; r < 8; ++r) {
        const int t = t0 + r;
        const float* p = xin + tok_base<GRIDMODE>(b, r0, c0, t);
        float v0 = p[lane];
        float v1 = p[lane + 32];
        float v2 = (lane < 16) ? p[lane + 64] : 0.f;
        float s  = warp_sum(v0*v0 + v1*v1 + v2*v2);
        float inv = 1.f / fmaxf(sqrtf(s), 1e-12f);
        xT[lane * TSTR + t]        = v0 * inv;
        xT[(lane + 32) * TSTR + t] = v1 * inv;
        if (lane < 16) xT[(lane + 64) * TSTR + t] = v2 * inv;
    }
    __syncwarp();

    // ---- phase 2: qkv = xn @ Wqkv + b (packed token-pairs), 2 halves of 4 cols
    #pragma unroll 1
    for (int half = 0; half < 2; ++half) {
        int cs[4];
        u64 acc[4][4];                  // [token-pair][col]
        #pragma unroll
        for (int g = 0; g < 4; ++g) {
            int c = lane + 32 * (half * 4 + g);
            cs[g] = (c < 240) ? c : 239;
            u64 bz = dup2(bqkv[cs[g]]);
            #pragma unroll
            for (int p = 0; p < 4; ++p) acc[p][g] = bz;
        }
        #pragma unroll 2
        for (int j = 0; j < CC; ++j) {
            u64 xp[4];
            #pragma unroll
            for (int p = 0; p < 4; ++p)
                xp[p] = *reinterpret_cast<const u64*>(xT + j * TSTR + t0 + 2 * p);
            const float* wrow = wqkv + j * 240;
            u64 wp[4];
            #pragma unroll
            for (int g = 0; g < 4; ++g) wp[g] = dup2(__ldg(wrow + cs[g]));
            #pragma unroll
            for (int g = 0; g < 4; ++g)
                #pragma unroll
                for (int p = 0; p < 4; ++p)
                    acc[p][g] = fma2(xp[p], wp[g], acc[p][g]);
        }
        #pragma unroll
        for (int g = 0; g < 4; ++g) {
            int c = lane + 32 * (half * 4 + g);
            if (c < 240) {
                int hd = c / 30, rm = c % 30, s3 = rm / 10, d = rm % 10;
                float* dst = ((s3 == 0) ? sq : (s3 == 1) ? sk : sv) + hd * DHH + d;
                #pragma unroll
                for (int p = 0; p < 4; ++p) {
                    float lo, hi; unpack2(acc[p][g], lo, hi);
                    dst[(t0 + 2*p)     * CC] = lo;
                    dst[(t0 + 2*p + 1) * CC] = hi;
                }
            }
        }
    }
    __syncthreads();

    // ---- phase 3: attention, one head per warp, packed over d, exp2 softmax ----
    {
        const int hd = wid;
        const float* qb = sq + hd * DHH;
        const float* kb = sk + hd * DHH;
        const float* vb = sv + hd * DHH;
        const float qscale = 0.31622776601683794f * 1.4426950408889634f;
        const u64 qs2 = dup2(qscale);
        u64 q0p[5], q1p[5], o0p[5], o1p[5];
        #pragma unroll
        for (int d2 = 0; d2 < 5; ++d2) {
            q0p[d2] = mul2(*reinterpret_cast<const u64*>(qb + lane * CC + 2*d2), qs2);
            q1p[d2] = mul2(*reinterpret_cast<const u64*>(qb + (lane+32) * CC + 2*d2), qs2);
            o0p[d2] = 0ull; o1p[d2] = 0ull;
        }
        float m0 = -1e30f, m1 = -1e30f, l0 = 0.f, l1 = 0.f;
        #pragma unroll 2
        for (int kk = 0; kk < 64; ++kk) {
            u64 kp[5], vp[5];
            #pragma unroll
            for (int d2 = 0; d2 < 5; ++d2) {
                kp[d2] = *reinterpret_cast<const u64*>(kb + kk * CC + 2*d2);
                vp[d2] = *reinterpret_cast<const u64*>(vb + kk * CC + 2*d2);
            }
            u64 a0 = mul2(q0p[0], kp[0]);
            u64 a1 = mul2(q1p[0], kp[0]);
            #pragma unroll
            for (int d2 = 1; d2 < 5; ++d2) {
                a0 = fma2(q0p[d2], kp[d2], a0);
                a1 = fma2(q1p[d2], kp[d2], a1);
            }
            float s0a, s0b, s1a, s1b;
            unpack2(a0, s0a, s0b); unpack2(a1, s1a, s1b);
            float s0 = s0a + s0b, s1 = s1a + s1b;

            float nm0 = fmaxf(m0, s0);
            float cf0 = exp2f(m0 - nm0);
            float p0  = exp2f(s0 - nm0);
            l0 = l0 * cf0 + p0;
            m0 = nm0;
            u64 cf0d = dup2(cf0), p0d = dup2(p0);
            #pragma unroll
            for (int d2 = 0; d2 < 5; ++d2)
                o0p[d2] = fma2(o0p[d2], cf0d, mul2(p0d, vp[d2]));

            float nm1 = fmaxf(m1, s1);
            float cf1 = exp2f(m1 - nm1);
            float p1  = exp2f(s1 - nm1);
            l1 = l1 * cf1 + p1;
            m1 = nm1;
            u64 cf1d = dup2(cf1), p1d = dup2(p1);
            #pragma unroll
            for (int d2 = 0; d2 < 5; ++d2)
                o1p[d2] = fma2(o1p[d2], cf1d, mul2(p1d, vp[d2]));
        }
        const float il0 = 1.f / l0, il1 = 1.f / l1;
        #pragma unroll
        for (int d2 = 0; d2 < 5; ++d2) {
            float lo, hi;
            unpack2(o0p[d2], lo, hi);
            oT[(hd * DHH + 2*d2)     * TSTR + lane] = lo * il0;
            oT[(hd * DHH + 2*d2 + 1) * TSTR + lane] = hi * il0;
            unpack2(o1p[d2], lo, hi);
            oT[(hd * DHH + 2*d2)     * TSTR + lane + 32] = lo * il1;
            oT[(hd * DHH + 2*d2 + 1) * TSTR + lane + 32] = hi * il1;
        }
    }
    __syncthreads();

    // ---- phase 4: proj + residual + scatter (packed token-pairs) ----
    {
        int cs[3];
        cs[0] = lane; cs[1] = lane + 32; cs[2] = (lane < 16) ? (lane + 64) : 79;
        u64 acc[4][3];
        #pragma unroll
        for (int g = 0; g < 3; ++g) {
            u64 bz = dup2(bproj[cs[g]]);
            #pragma unroll
            for (int p = 0; p < 4; ++p) acc[p][g] = bz;
        }
        #pragma unroll 2
        for (int j = 0; j < CC; ++j) {
            u64 op[4];
            #pragma unroll
            for (int p = 0; p < 4; ++p)
                op[p] = *reinterpret_cast<const u64*>(oT + j * TSTR + t0 + 2 * p);
            const float* wrow = wproj + j * CC;
            u64 wp[3];
            #pragma unroll
            for (int g = 0; g < 3; ++g) wp[g] = dup2(__ldg(wrow + cs[g]));
            #pragma unroll
            for (int g = 0; g < 3; ++g)
                #pragma unroll
                for (int p = 0; p < 4; ++p)
                    acc[p][g] = fma2(op[p], wp[g], acc[p][g]);
        }
        #pragma unroll
        for (int p = 0; p < 4; ++p) {
            const int ta = t0 + 2*p, tb = ta + 1;
            const size_t ba = tok_base<GRIDMODE>(b, r0, c0, ta);
            const size_t bb = tok_base<GRIDMODE>(b, r0, c0, tb);
            #pragma unroll
            for (int g = 0; g < 3; ++g) {
                if (g < 2 || lane < 16) {
                    float lo, hi; unpack2(acc[p][g], lo, hi);
                    yout[ba + cs[g]] = xT[cs[g] * TSTR + ta] + lo;
                    yout[bb + cs[g]] = xT[cs[g] * TSTR + tb] + hi;
                }
            }
        }
    }
}

// ============================================================================
// MLP kernel: one CTA per 64 contiguous tokens. smem ~103KB -> 2 CTAs/SM.
// Fully warp-local (warp owns its 8 tokens) -> no CTA-wide syncs.
// ============================================================================
template<bool RELU2>
__global__ __launch_bounds__(256, 2)
void mlp_kernel(const float* __restrict__ xin,
                const float* __restrict__ w1,
                const float* __restrict__ w2,
                const float* __restrict__ b2,
                const float* __restrict__ gamma,
                float* __restrict__ yout)
{
    extern __shared__ float sm[];
    float* xT = sm;             // 80  x 66 = 5280
    float* hT = sm + 5280;      // 320 x 66 = 21120   (total 26400 fl)

    const int tid  = threadIdx.x;
    const int lane = tid & 31;
    const int wid  = tid >> 5;
    const int t0   = wid * 8;
    const size_t base = (size_t)blockIdx.x * 64 * CC;

    // ---- load + l2norm -> xT ----
    #pragma unroll
    for (int r = 0; r < 8; ++r) {
        const int t = t0 + r;
        const float* p = xin + base + (size_t)t * CC;
        float v0 = p[lane];
        float v1 = p[lane + 32];
        float v2 = (lane < 16) ? p[lane + 64] : 0.f;
        float s  = warp_sum(v0*v0 + v1*v1 + v2*v2);
        float inv = 1.f / fmaxf(sqrtf(s), 1e-12f);
        xT[lane * TSTR + t]        = v0 * inv;
        xT[(lane + 32) * TSTR + t] = v1 * inv;
        if (lane < 16) xT[(lane + 64) * TSTR + t] = v2 * inv;
    }
    __syncwarp();

    // ---- h = relu(xn @ W1): 2 halves of 5 cols, packed token-pairs ----
    #pragma unroll 1
    for (int half = 0; half < 2; ++half) {
        const int cbase = half * 160 + lane;
        u64 acc[4][5];
        #pragma unroll
        for (int g = 0; g < 5; ++g)
            #pragma unroll
            for (int p = 0; p < 4; ++p) acc[p][g] = 0ull;
        #pragma unroll 2
        for (int j = 0; j < CC; ++j) {
            u64 xp[4];
            #pragma unroll
            for (int p = 0; p < 4; ++p)
                xp[p] = *reinterpret_cast<const u64*>(xT + j * TSTR + t0 + 2 * p);
            const float* wrow = w1 + j * 320 + cbase;
            u64 wp[5];
            #pragma unroll
            for (int g = 0; g < 5; ++g) wp[g] = dup2(__ldg(wrow + 32 * g));
            #pragma unroll
            for (int g = 0; g < 5; ++g)
                #pragma unroll
                for (int p = 0; p < 4; ++p)
                    acc[p][g] = fma2(xp[p], wp[g], acc[p][g]);
        }
        #pragma unroll
        for (int g = 0; g < 5; ++g) {
            float* hc = hT + (cbase + 32 * g) * TSTR + t0;
            #pragma unroll
            for (int p = 0; p < 4; ++p) {
                float lo, hi; unpack2(acc[p][g], lo, hi);
                hc[2*p]     = fmaxf(lo, 0.f);
                hc[2*p + 1] = fmaxf(hi, 0.f);
            }
        }
    }
    __syncwarp();

    // ---- out = xn + act(h @ W2 + b2) * gamma ----
    {
        int cs[3];
        cs[0] = lane; cs[1] = lane + 32; cs[2] = (lane < 16) ? (lane + 64) : 79;
        u64 acc[4][3];
        #pragma unroll
        for (int g = 0; g < 3; ++g) {
            u64 bz = dup2(b2[cs[g]]);
            #pragma unroll
            for (int p = 0; p < 4; ++p) acc[p][g] = bz;
        }
        #pragma unroll 2
        for (int j = 0; j < 320; ++j) {
            u64 hp[4];
            #pragma unroll
            for (int p = 0; p < 4; ++p)
                hp[p] = *reinterpret_cast<const u64*>(hT + j * TSTR + t0 + 2 * p);
            const float* wrow = w2 + j * CC;
            u64 wp[3];
            #pragma unroll
            for (int g = 0; g < 3; ++g) wp[g] = dup2(__ldg(wrow + cs[g]));
            #pragma unroll
            for (int g = 0; g < 3; ++g)
                #pragma unroll
                for (int p = 0; p < 4; ++p)
                    acc[p][g] = fma2(hp[p], wp[g], acc[p][g]);
        }
        #pragma unroll
        for (int g = 0; g < 3; ++g) {
            if (g < 2 || lane < 16) {
                const float gm = gamma[cs[g]];
                #pragma unroll
                for (int p = 0; p < 4; ++p) {
                    const int ta = t0 + 2*p, tb = ta + 1;
                    float lo, hi; unpack2(acc[p][g], lo, hi);
                    if (RELU2) { lo = fmaxf(lo, 0.f); hi = fmaxf(hi, 0.f); }
                    yout[base + (size_t)ta * CC + cs[g]] = xT[cs[g] * TSTR + ta] + lo * gm;
                    yout[base + (size_t)tb * CC + cs[g]] = xT[cs[g] * TSTR + tb] + hi * gm;
                }
            }
        }
    }
}

// ============================================================================
extern "C" void kernel_launch(void* const* d_in, const int* in_sizes, int n_in,
                              void* d_out, int out_size)
{
    const float* x       = (const float*)d_in[0];
    const float* bw_qkv  = (const float*)d_in[1];
    const float* bb_qkv  = (const float*)d_in[2];
    const float* bw_proj = (const float*)d_in[3];
    const float* bb_proj = (const float*)d_in[4];
    const float* b_gamma = (const float*)d_in[5];
    const float* bw_mlp1 = (const float*)d_in[6];
    const float* bw_mlp2 = (const float*)d_in[7];
    const float* bb_mlp2 = (const float*)d_in[8];
    const float* gw_qkv  = (const float*)d_in[9];
    const float* gb_qkv  = (const float*)d_in[10];
    const float* gw_proj = (const float*)d_in[11];
    const float* gb_proj = (const float*)d_in[12];
    const float* g_gamma = (const float*)d_in[13];
    const float* gw_mlp1 = (const float*)d_in[14];
    const float* gw_mlp2 = (const float*)d_in[15];
    const float* gb_mlp2 = (const float*)d_in[16];
    float* out = (float*)d_out;

    float *t1 = nullptr, *t2 = nullptr;
    cudaGetSymbolAddress((void**)&t1, g_t1);
    cudaGetSymbolAddress((void**)&t2, g_t2);

    const int ATTN_SMEM = 25920 * (int)sizeof(float);  // 103680
    const int MLP_SMEM  = 26400 * (int)sizeof(float);  // 105600

    static bool attrs_set = false;
    if (!attrs_set) {
        cudaFuncSetAttribute(attn_kernel<false>, cudaFuncAttributeMaxDynamicSharedMemorySize, ATTN_SMEM);
        cudaFuncSetAttribute(attn_kernel<true>,  cudaFuncAttributeMaxDynamicSharedMemorySize, ATTN_SMEM);
        cudaFuncSetAttribute(mlp_kernel<true>,   cudaFuncAttributeMaxDynamicSharedMemorySize, MLP_SMEM);
        cudaFuncSetAttribute(mlp_kernel<false>,  cudaFuncAttributeMaxDynamicSharedMemorySize, MLP_SMEM);
        attrs_set = true;
    }

    const int NB_MLP = NTOK / 64;   // 8192

    attn_kernel<false><<<NWIN, 256, ATTN_SMEM>>>(x,  bw_qkv, bb_qkv, bw_proj, bb_proj, t1);
    mlp_kernel<true><<<NB_MLP, 256, MLP_SMEM>>>(t1, bw_mlp1, bw_mlp2, bb_mlp2, b_gamma, t2);
    attn_kernel<true><<<NWIN, 256, ATTN_SMEM>>>(t2, gw_qkv, gb_qkv, gw_proj, gb_proj, t1);
    mlp_kernel<false><<<NB_MLP, 256, MLP_SMEM>>>(t1, gw_mlp1, gw_mlp2, gb_mlp2, g_gamma, out);
}

// round 8
// speedup vs baseline: 2.4105x; 2.3841x over previous
#include <cuda_runtime.h>
#include <math.h>
#include <stdint.h>

#define BB   32
#define HH   128
#define WWD  128
#define CC   80
#define DHH  10
#define NHH  8
#define NTOK (BB*HH*WWD)      // 524288
#define NWIN 8192
#define XSTR 84               // xn / O row stride (conflict-free A-frag loads)
#define HSTR 324              // H row stride

// ---- scratch (allocation-free: device globals) ----
__device__ float g_t1[(size_t)NTOK * CC];
__device__ float g_t2[(size_t)NTOK * CC];
// packed tf32 weights, fragment-major: [ntile][kpair][lane][4]
#define PK_BQKV   0
#define PK_BPROJ  19200
#define PK_BMLP1  25600
#define PK_BMLP2  51200
#define PK_GQKV   76800
#define PK_GPROJ  96000
#define PK_GMLP1  102400
#define PK_GMLP2  128000
#define PK_TOTAL  153600
__device__ float g_wpk[PK_TOTAL];

// ---- helpers ----
__device__ __forceinline__ uint32_t cvt_tf32(float f) {
    uint32_t r; asm("cvt.rna.tf32.f32 %0, %1;" : "=r"(r) : "f"(f)); return r;
}
__device__ __forceinline__ void mma8(float* acc, const uint32_t* a, uint32_t b0, uint32_t b1) {
    asm("mma.sync.aligned.m16n8k8.row.col.f32.tf32.tf32.f32 "
        "{%0,%1,%2,%3}, {%4,%5,%6,%7}, {%8,%9}, {%0,%1,%2,%3};"
        : "+f"(acc[0]), "+f"(acc[1]), "+f"(acc[2]), "+f"(acc[3])
        : "r"(a[0]), "r"(a[1]), "r"(a[2]), "r"(a[3]), "r"(b0), "r"(b1));
}
__device__ __forceinline__ float warp_sum(float v) {
    v += __shfl_xor_sync(0xffffffffu, v, 16);
    v += __shfl_xor_sync(0xffffffffu, v, 8);
    v += __shfl_xor_sync(0xffffffffu, v, 4);
    v += __shfl_xor_sync(0xffffffffu, v, 2);
    v += __shfl_xor_sync(0xffffffffu, v, 1);
    return v;
}

template<bool GRIDMODE>
__device__ __forceinline__ size_t tok_base(int b, int r0, int c0, int t) {
    int i = t >> 3, j = t & 7;
    int hh, ww;
    if (!GRIDMODE) { hh = r0 * 8 + i;  ww = c0 * 8 + j;  }
    else           { hh = i * 16 + r0; ww = j * 16 + c0; }
    return ((size_t)((b * HH + hh) * WWD + ww)) * CC;
}

// ---- weight pack: W[K x N] row-major -> frag-major tf32 ----
// P[((nt*KP + kp)*32 + lane)*4 + q]:
//   ks = kp*2 + (q>>1); row = ks*8 + (lane&3) + 4*(q&1); col = nt*8 + (lane>>2)
__global__ void pack_w(const float* __restrict__ W, float* __restrict__ P, int K, int N) {
    const int total = (N >> 3) * (K >> 4) * 128;
    const int KP = K >> 4;
    for (int idx = blockIdx.x * blockDim.x + threadIdx.x; idx < total;
         idx += gridDim.x * blockDim.x) {
        int q    = idx & 3;
        int lane = (idx >> 2) & 31;
        int rest = idx >> 7;
        int kp   = rest % KP;
        int nt   = rest / KP;
        int ks   = kp * 2 + (q >> 1);
        int row  = ks * 8 + (lane & 3) + ((q & 1) << 2);
        int col  = nt * 8 + (lane >> 2);
        P[idx] = __uint_as_float(cvt_tf32(W[row * N + col]));
    }
}

// A-fragment loader from smem row-major (stride S), with cvt to tf32
__device__ __forceinline__ void load_afrag_cvt(uint32_t af[4], const float* base,
                                               int S, int g, int tg) {
    af[0] = cvt_tf32(base[(g    ) * S + tg    ]);
    af[1] = cvt_tf32(base[(g + 8) * S + tg    ]);
    af[2] = cvt_tf32(base[(g    ) * S + tg + 4]);
    af[3] = cvt_tf32(base[(g + 8) * S + tg + 4]);
}

// ============================================================================
// Attention kernel: one CTA / 64-token window, 256 thr, smem 102KB, 2 CTAs/SM
// ============================================================================
template<bool GRIDMODE>
__global__ __launch_bounds__(256, 2)
void attn_kernel(const float* __restrict__ xin,
                 const float* __restrict__ bqkv,
                 const float* __restrict__ bproj,
                 const float* __restrict__ pk_qkv,
                 const float* __restrict__ pk_proj,
                 float* __restrict__ yout)
{
    extern __shared__ float smf[];
    float* xn = smf;                       // 64 x 84 = 5376
    float* sq = smf + 5376;                // 64 x 80
    float* sk = smf + 5376 + 5120;
    float* sv = smf + 5376 + 10240;
    float* oT = smf + 5376 + 15360;        // 64 x 84

    const int tid  = threadIdx.x;
    const int lane = tid & 31;
    const int wid  = tid >> 5;

    const int wblk = blockIdx.x;
    const int b    = wblk >> 8;
    const int rem  = wblk & 255;
    const int r0   = rem >> 4;
    const int c0   = rem & 15;

    // ---- phase 1: load + l2norm -> xn (warp owns 8 tokens) ----
    #pragma unroll
    for (int r = 0; r < 8; ++r) {
        const int t = wid * 8 + r;
        const float* p = xin + tok_base<GRIDMODE>(b, r0, c0, t);
        float v0 = p[lane];
        float v1 = p[lane + 32];
        float v2 = (lane < 16) ? p[lane + 64] : 0.f;
        float s  = warp_sum(v0*v0 + v1*v1 + v2*v2);
        float inv = 1.f / fmaxf(sqrtf(s), 1e-12f);
        float* xr = xn + t * XSTR;
        xr[lane]      = v0 * inv;
        xr[lane + 32] = v1 * inv;
        if (lane < 16) xr[lane + 64] = v2 * inv;
    }
    __syncthreads();

    // ---- phase 2: qkv via tf32 mma. warp = (mtile, nhalf); 15 ntiles each ----
    {
        const int mt = wid >> 1, ng = wid & 1;
        const int g = lane >> 2, tg = lane & 3;
        const float* ar = xn + (mt * 16) * XSTR;
        uint32_t af[10][4];
        #pragma unroll
        for (int ks = 0; ks < 10; ++ks)
            load_afrag_cvt(af[ks], ar + ks * 8, XSTR, g, tg);
        const int tok0 = mt * 16 + g, tok1 = tok0 + 8;
        #pragma unroll 1
        for (int nt0 = 0; nt0 < 15; ++nt0) {
            const int nt = ng * 15 + nt0;
            float acc[4] = {0.f, 0.f, 0.f, 0.f};
            const float4* bp = reinterpret_cast<const float4*>(pk_qkv + (size_t)nt * 5 * 128) + lane;
            #pragma unroll
            for (int kp = 0; kp < 5; ++kp) {
                float4 bv = __ldg(bp + kp * 32);
                mma8(acc, af[2*kp],     __float_as_uint(bv.x), __float_as_uint(bv.y));
                mma8(acc, af[2*kp + 1], __float_as_uint(bv.z), __float_as_uint(bv.w));
            }
            const int cA = nt * 8 + 2 * tg, cB = cA + 1;
            const float bA = __ldg(bqkv + cA), bB = __ldg(bqkv + cB);
            {
                int hd = cA / 30, rm = cA - hd * 30, s3 = rm / 10, d = rm - s3 * 10;
                float* dst = ((s3 == 0) ? sq : (s3 == 1) ? sk : sv) + hd * DHH + d;
                dst[tok0 * 80] = acc[0] + bA;
                dst[tok1 * 80] = acc[2] + bA;
            }
            {
                int hd = cB / 30, rm = cB - hd * 30, s3 = rm / 10, d = rm - s3 * 10;
                float* dst = ((s3 == 0) ? sq : (s3 == 1) ? sk : sv) + hd * DHH + d;
                dst[tok0 * 80] = acc[1] + bB;
                dst[tok1 * 80] = acc[3] + bB;
            }
        }
    }
    __syncthreads();

    // ---- phase 3: scalar attention, one head per warp, exp2 softmax ----
    {
        const int hd = wid;
        const float* qb = sq + hd * DHH;
        const float* kb = sk + hd * DHH;
        const float* vb = sv + hd * DHH;
        const float qscale = 0.31622776601683794f * 1.4426950408889634f;
        float q0[10], q1[10], o0[10], o1[10];
        #pragma unroll
        for (int d = 0; d < 10; ++d) {
            q0[d] = qb[lane * 80 + d] * qscale;
            q1[d] = qb[(lane + 32) * 80 + d] * qscale;
            o0[d] = 0.f; o1[d] = 0.f;
        }
        float m0 = -1e30f, m1 = -1e30f, l0 = 0.f, l1 = 0.f;
        #pragma unroll 2
        for (int kk = 0; kk < 64; ++kk) {
            float kv[10], vv[10];
            #pragma unroll
            for (int d2 = 0; d2 < 5; ++d2) {
                float2 kt = *reinterpret_cast<const float2*>(kb + kk * 80 + 2 * d2);
                float2 vt = *reinterpret_cast<const float2*>(vb + kk * 80 + 2 * d2);
                kv[2*d2] = kt.x; kv[2*d2+1] = kt.y;
                vv[2*d2] = vt.x; vv[2*d2+1] = vt.y;
            }
            float s0 = 0.f, s1 = 0.f;
            #pragma unroll
            for (int d = 0; d < 10; ++d) { s0 = fmaf(q0[d], kv[d], s0); s1 = fmaf(q1[d], kv[d], s1); }

            float nm0 = fmaxf(m0, s0);
            float cf0 = exp2f(m0 - nm0);
            float p0  = exp2f(s0 - nm0);
            l0 = l0 * cf0 + p0;  m0 = nm0;
            #pragma unroll
            for (int d = 0; d < 10; ++d) o0[d] = fmaf(o0[d], cf0, p0 * vv[d]);

            float nm1 = fmaxf(m1, s1);
            float cf1 = exp2f(m1 - nm1);
            float p1  = exp2f(s1 - nm1);
            l1 = l1 * cf1 + p1;  m1 = nm1;
            #pragma unroll
            for (int d = 0; d < 10; ++d) o1[d] = fmaf(o1[d], cf1, p1 * vv[d]);
        }
        const float il0 = 1.f / l0, il1 = 1.f / l1;
        #pragma unroll
        for (int d = 0; d < 10; ++d) {
            oT[lane        * XSTR + hd * DHH + d] = o0[d] * il0;
            oT[(lane + 32) * XSTR + hd * DHH + d] = o1[d] * il1;
        }
    }
    __syncthreads();

    // ---- phase 4: proj via tf32 mma + residual + scatter ----
    {
        const int mt = wid >> 1, ng = wid & 1;
        const int g = lane >> 2, tg = lane & 3;
        const float* ar = oT + (mt * 16) * XSTR;
        uint32_t af[10][4];
        #pragma unroll
        for (int ks = 0; ks < 10; ++ks)
            load_afrag_cvt(af[ks], ar + ks * 8, XSTR, g, tg);
        const int tok0 = mt * 16 + g, tok1 = tok0 + 8;
        const size_t base0 = tok_base<GRIDMODE>(b, r0, c0, tok0);
        const size_t base1 = tok_base<GRIDMODE>(b, r0, c0, tok1);
        #pragma unroll 1
        for (int nt0 = 0; nt0 < 5; ++nt0) {
            const int nt = ng * 5 + nt0;
            float acc[4] = {0.f, 0.f, 0.f, 0.f};
            const float4* bp = reinterpret_cast<const float4*>(pk_proj + (size_t)nt * 5 * 128) + lane;
            #pragma unroll
            for (int kp = 0; kp < 5; ++kp) {
                float4 bv = __ldg(bp + kp * 32);
                mma8(acc, af[2*kp],     __float_as_uint(bv.x), __float_as_uint(bv.y));
                mma8(acc, af[2*kp + 1], __float_as_uint(bv.z), __float_as_uint(bv.w));
            }
            const int cA = nt * 8 + 2 * tg, cB = cA + 1;
            const float bA = __ldg(bproj + cA), bB = __ldg(bproj + cB);
            yout[base0 + cA] = xn[tok0 * XSTR + cA] + acc[0] + bA;
            yout[base0 + cB] = xn[tok0 * XSTR + cB] + acc[1] + bB;
            yout[base1 + cA] = xn[tok1 * XSTR + cA] + acc[2] + bA;
            yout[base1 + cB] = xn[tok1 * XSTR + cB] + acc[3] + bB;
        }
    }
}

// ============================================================================
// MLP kernel: one CTA / 64 contiguous tokens, smem 102KB, 2 CTAs/SM
// ============================================================================
template<bool RELU2>
__global__ __launch_bounds__(256, 2)
void mlp_kernel(const float* __restrict__ xin,
                const float* __restrict__ pw1,
                const float* __restrict__ pw2,
                const float* __restrict__ b2,
                const float* __restrict__ gamma,
                float* __restrict__ yout)
{
    extern __shared__ float smf[];
    float* xn = smf;               // 64 x 84
    float* hT = smf + 5376;        // 64 x 324 (tf32 bits as float)

    const int tid  = threadIdx.x;
    const int lane = tid & 31;
    const int wid  = tid >> 5;
    const size_t base = (size_t)blockIdx.x * 64 * CC;

    // ---- phase 1: load + l2norm ----
    #pragma unroll
    for (int r = 0; r < 8; ++r) {
        const int t = wid * 8 + r;
        const float* p = xin + base + (size_t)t * CC;
        float v0 = p[lane];
        float v1 = p[lane + 32];
        float v2 = (lane < 16) ? p[lane + 64] : 0.f;
        float s  = warp_sum(v0*v0 + v1*v1 + v2*v2);
        float inv = 1.f / fmaxf(sqrtf(s), 1e-12f);
        float* xr = xn + t * XSTR;
        xr[lane]      = v0 * inv;
        xr[lane + 32] = v1 * inv;
        if (lane < 16) xr[lane + 64] = v2 * inv;
    }
    __syncthreads();

    const int mt = wid >> 1, ng = wid & 1;
    const int g = lane >> 2, tg = lane & 3;
    const int tok0 = mt * 16 + g, tok1 = tok0 + 8;

    // ---- phase 2: H = relu(xn @ W1) -> tf32 in smem ----
    {
        const float* ar = xn + (mt * 16) * XSTR;
        uint32_t af[10][4];
        #pragma unroll
        for (int ks = 0; ks < 10; ++ks)
            load_afrag_cvt(af[ks], ar + ks * 8, XSTR, g, tg);
        #pragma unroll 1
        for (int nt0 = 0; nt0 < 20; ++nt0) {
            const int nt = ng * 20 + nt0;
            float acc[4] = {0.f, 0.f, 0.f, 0.f};
            const float4* bp = reinterpret_cast<const float4*>(pw1 + (size_t)nt * 5 * 128) + lane;
            #pragma unroll
            for (int kp = 0; kp < 5; ++kp) {
                float4 bv = __ldg(bp + kp * 32);
                mma8(acc, af[2*kp],     __float_as_uint(bv.x), __float_as_uint(bv.y));
                mma8(acc, af[2*kp + 1], __float_as_uint(bv.z), __float_as_uint(bv.w));
            }
            const int c0 = nt * 8 + 2 * tg, c1 = c0 + 1;
            hT[tok0 * HSTR + c0] = __uint_as_float(cvt_tf32(fmaxf(acc[0], 0.f)));
            hT[tok0 * HSTR + c1] = __uint_as_float(cvt_tf32(fmaxf(acc[1], 0.f)));
            hT[tok1 * HSTR + c0] = __uint_as_float(cvt_tf32(fmaxf(acc[2], 0.f)));
            hT[tok1 * HSTR + c1] = __uint_as_float(cvt_tf32(fmaxf(acc[3], 0.f)));
        }
    }
    __syncthreads();

    // ---- phase 3: out = xn + act(H @ W2 + b2) * gamma ----
    {
        float acc[5][4];
        #pragma unroll
        for (int n = 0; n < 5; ++n)
            #pragma unroll
            for (int i = 0; i < 4; ++i) acc[n][i] = 0.f;
        const float* hr = hT + (mt * 16) * HSTR;
        #pragma unroll 1
        for (int kp = 0; kp < 20; ++kp) {
            const int k0 = kp * 16;
            uint32_t a0[4], a1[4];
            a0[0] = __float_as_uint(hr[(g    ) * HSTR + k0 + tg    ]);
            a0[1] = __float_as_uint(hr[(g + 8) * HSTR + k0 + tg    ]);
            a0[2] = __float_as_uint(hr[(g    ) * HSTR + k0 + tg + 4]);
            a0[3] = __float_as_uint(hr[(g + 8) * HSTR + k0 + tg + 4]);
            a1[0] = __float_as_uint(hr[(g    ) * HSTR + k0 + 8 + tg    ]);
            a1[1] = __float_as_uint(hr[(g + 8) * HSTR + k0 + 8 + tg    ]);
            a1[2] = __float_as_uint(hr[(g    ) * HSTR + k0 + 8 + tg + 4]);
            a1[3] = __float_as_uint(hr[(g + 8) * HSTR + k0 + 8 + tg + 4]);
            #pragma unroll
            for (int nt0 = 0; nt0 < 5; ++nt0) {
                const int nt = ng * 5 + nt0;
                const float4* bp = reinterpret_cast<const float4*>(
                    pw2 + ((size_t)nt * 20 + kp) * 128) + lane;
                float4 bv = __ldg(bp);
                mma8(acc[nt0], a0, __float_as_uint(bv.x), __float_as_uint(bv.y));
                mma8(acc[nt0], a1, __float_as_uint(bv.z), __float_as_uint(bv.w));
            }
        }
        #pragma unroll
        for (int nt0 = 0; nt0 < 5; ++nt0) {
            const int nt = ng * 5 + nt0;
            const int c0 = nt * 8 + 2 * tg, c1 = c0 + 1;
            const float bA = __ldg(b2 + c0), bB = __ldg(b2 + c1);
            const float gA = __ldg(gamma + c0), gB = __ldg(gamma + c1);
            float v00 = acc[nt0][0] + bA, v01 = acc[nt0][1] + bB;
            float v10 = acc[nt0][2] + bA, v11 = acc[nt0][3] + bB;
            if (RELU2) {
                v00 = fmaxf(v00, 0.f); v01 = fmaxf(v01, 0.f);
                v10 = fmaxf(v10, 0.f); v11 = fmaxf(v11, 0.f);
            }
            yout[base + (size_t)tok0 * CC + c0] = xn[tok0 * XSTR + c0] + v00 * gA;
            yout[base + (size_t)tok0 * CC + c1] = xn[tok0 * XSTR + c1] + v01 * gB;
            yout[base + (size_t)tok1 * CC + c0] = xn[tok1 * XSTR + c0] + v10 * gA;
            yout[base + (size_t)tok1 * CC + c1] = xn[tok1 * XSTR + c1] + v11 * gB;
        }
    }
}

// ============================================================================
extern "C" void kernel_launch(void* const* d_in, const int* in_sizes, int n_in,
                              void* d_out, int out_size)
{
    const float* x       = (const float*)d_in[0];
    const float* bw_qkv  = (const float*)d_in[1];
    const float* bb_qkv  = (const float*)d_in[2];
    const float* bw_proj = (const float*)d_in[3];
    const float* bb_proj = (const float*)d_in[4];
    const float* b_gamma = (const float*)d_in[5];
    const float* bw_mlp1 = (const float*)d_in[6];
    const float* bw_mlp2 = (const float*)d_in[7];
    const float* bb_mlp2 = (const float*)d_in[8];
    const float* gw_qkv  = (const float*)d_in[9];
    const float* gb_qkv  = (const float*)d_in[10];
    const float* gw_proj = (const float*)d_in[11];
    const float* gb_proj = (const float*)d_in[12];
    const float* g_gamma = (const float*)d_in[13];
    const float* gw_mlp1 = (const float*)d_in[14];
    const float* gw_mlp2 = (const float*)d_in[15];
    const float* gb_mlp2 = (const float*)d_in[16];
    float* out = (float*)d_out;

    float *t1 = nullptr, *t2 = nullptr, *pk = nullptr;
    cudaGetSymbolAddress((void**)&t1, g_t1);
    cudaGetSymbolAddress((void**)&t2, g_t2);
    cudaGetSymbolAddress((void**)&pk, g_wpk);

    const int ATTN_SMEM = 26112 * (int)sizeof(float);  // 104448
    const int MLP_SMEM  = 26112 * (int)sizeof(float);  // 104448

    static bool attrs_set = false;
    if (!attrs_set) {
        cudaFuncSetAttribute(attn_kernel<false>, cudaFuncAttributeMaxDynamicSharedMemorySize, ATTN_SMEM);
        cudaFuncSetAttribute(attn_kernel<true>,  cudaFuncAttributeMaxDynamicSharedMemorySize, ATTN_SMEM);
        cudaFuncSetAttribute(mlp_kernel<true>,   cudaFuncAttributeMaxDynamicSharedMemorySize, MLP_SMEM);
        cudaFuncSetAttribute(mlp_kernel<false>,  cudaFuncAttributeMaxDynamicSharedMemorySize, MLP_SMEM);
        attrs_set = true;
    }

    // ---- pack all weights to tf32 fragment-major ----
    pack_w<<<64, 256>>>(bw_qkv,  pk + PK_BQKV,  80, 240);
    pack_w<<<64, 256>>>(bw_proj, pk + PK_BPROJ, 80, 80);
    pack_w<<<64, 256>>>(bw_mlp1, pk + PK_BMLP1, 80, 320);
    pack_w<<<64, 256>>>(bw_mlp2, pk + PK_BMLP2, 320, 80);
    pack_w<<<64, 256>>>(gw_qkv,  pk + PK_GQKV,  80, 240);
    pack_w<<<64, 256>>>(gw_proj, pk + PK_GPROJ, 80, 80);
    pack_w<<<64, 256>>>(gw_mlp1, pk + PK_GMLP1, 80, 320);
    pack_w<<<64, 256>>>(gw_mlp2, pk + PK_GMLP2, 320, 80);

    const int NB = 8192;
    attn_kernel<false><<<NB, 256, ATTN_SMEM>>>(x,  bb_qkv, bb_proj, pk + PK_BQKV, pk + PK_BPROJ, t1);
    mlp_kernel<true><<<NB, 256, MLP_SMEM>>>(t1, pk + PK_BMLP1, pk + PK_BMLP2, bb_mlp2, b_gamma, t2);
    attn_kernel<true><<<NB, 256, ATTN_SMEM>>>(t2, gb_qkv, gb_proj, pk + PK_GQKV, pk + PK_GPROJ, t1);
    mlp_kernel<false><<<NB, 256, MLP_SMEM>>>(t1, pk + PK_GMLP1, pk + PK_GMLP2, gb_mlp2, g_gamma, out);
}